// round 5
// baseline (speedup 1.0000x reference)
#include <cuda_runtime.h>
#include <math.h>

// Problem constants
#define BB 64      // batch B
#define TT 256     // T
#define EE 64      // E (layer0 feature dim)
#define RR 4       // rel_dim
#define NSTACK 8   // n_stack
#define NEG_INF (-1e30f)

// -------- scratch (__device__ globals; no allocations) --------
__device__ float        g_partial[128 * BB * BB];  // split-K gram partials (2MB)
__device__ float        g_adj[BB * BB];            // sparsemax(adj) row-major
__device__ unsigned int g_gkey[BB * BB];           // merged window groups per row
__device__ float        g_gcnt[BB * BB];
__device__ int          g_ng[BB];
__device__ float        g_x1[BB * TT * RR];        // layer0 output
__device__ float        g_x2[BB * TT * RR];        // layer1 output

// =====================================================================
// Gram partial: one block per 128-wide K chunk; computes full 64x64
// partial gram of X (row-major, row stride = K) from an smem tile.
// USE_G1: read from g_x1 instead of the kernel argument.
// =====================================================================
template<int K, bool USE_G1>
__global__ void gram_partial_kernel(const float* __restrict__ Xin) {
    __shared__ float Xs[BB][129];   // pad to 129 to break bank conflicts
    const float* X = USE_G1 ? (const float*)g_x1 : Xin;
    const int blk = blockIdx.x;
    const int k0  = blk * 128;
    const int tid = threadIdx.x;    // 256 threads

    for (int i = tid; i < BB * 128; i += 256) {
        int r = i >> 7, c = i & 127;
        Xs[r][c] = X[r * K + k0 + c];
    }
    __syncthreads();

    const int tx = tid & 15, ty = tid >> 4;  // 16x16 threads, 4x4 micro-tile
    float acc[4][4];
#pragma unroll
    for (int i = 0; i < 4; ++i)
#pragma unroll
        for (int j = 0; j < 4; ++j) acc[i][j] = 0.f;

#pragma unroll 4
    for (int kk = 0; kk < 128; ++kk) {
        float a[4], b[4];
#pragma unroll
        for (int i = 0; i < 4; ++i) a[i] = Xs[ty * 4 + i][kk];
#pragma unroll
        for (int j = 0; j < 4; ++j) b[j] = Xs[tx * 4 + j][kk];
#pragma unroll
        for (int i = 0; i < 4; ++i)
#pragma unroll
            for (int j = 0; j < 4; ++j) acc[i][j] = fmaf(a[i], b[j], acc[i][j]);
    }

    float* dst = g_partial + blk * (BB * BB);
#pragma unroll
    for (int i = 0; i < 4; ++i)
#pragma unroll
        for (int j = 0; j < 4; ++j)
            dst[(ty * 4 + i) * BB + (tx * 4 + j)] = acc[i][j];
}

// =====================================================================
// Reduce partials -> z row, sparsemax (exact replica of reference
// semantics incl. tie handling), then build merged window groups:
// window for output b is [b-1, b+2] clipped to [0,63] (SAME, pool=4).
// Group key packs up to 4 support member indices (6b each), nm, zero flag.
// =====================================================================
template<int NSPLIT>
__global__ void finish_sparsemax_kernel() {
    const int row = blockIdx.x;
    const int tid = threadIdx.x;   // 64 threads

    __shared__ float z[BB], zs[BB], cum[BB], av[BB], cntb[BB];
    __shared__ unsigned int keys[BB];
    __shared__ int lead[BB];
    __shared__ float tau_s;

    float s = 0.f;
#pragma unroll 4
    for (int p = 0; p < NSPLIT; ++p) s += g_partial[p * (BB * BB) + row * BB + tid];
    const float zi = s * (1.0f / (float)TT);
    z[tid] = zi;
    __syncthreads();

    // rank (descending, index tiebreak) -> sorted array
    int r = 0;
    for (int j = 0; j < BB; ++j) {
        float zj = z[j];
        r += (zj > zi) || (zj == zi && j < tid);
    }
    zs[r] = zi;
    __syncthreads();

    if (tid == 0) {
        float c = 0.f; int ksel = 0;
        for (int j = 0; j < BB; ++j) {
            c += zs[j];
            cum[j] = c;
            if (1.0f + (float)(j + 1) * zs[j] > c) ksel++;
        }
        tau_s = (cum[ksel - 1] - 1.0f) / (float)ksel;
    }
    __syncthreads();

    const float a = fmaxf(zi - tau_s, 0.0f);
    av[tid] = a;
    g_adj[row * BB + tid] = a;
    __syncthreads();

    // per-window (b = tid) support member key
    const int lo = (tid - 1 > 0) ? tid - 1 : 0;
    const int hi = (tid + 2 < BB - 1) ? tid + 2 : BB - 1;
    int nm = 0;
    unsigned int key = 0u;
    for (int bp = lo; bp <= hi; ++bp)
        if (av[bp] > 0.0f) { key |= ((unsigned)bp) << (6 * nm); nm++; }
    const int wsz = hi - lo + 1;
    if (nm == 0) key = 0xFFFFFFFFu;                 // empty window -> 0 contribution
    else key |= ((unsigned)nm << 24) | ((nm < wsz ? 1u : 0u) << 28);
    keys[tid] = key;
    __syncthreads();

    // count duplicates + elect leaders
    int cnt = 0, leader = (key != 0xFFFFFFFFu);
    if (leader) {
        for (int j = 0; j < BB; ++j) {
            cnt += (keys[j] == key);
            if (keys[j] == key && j < tid) leader = 0;
        }
    }
    cntb[tid] = (float)cnt;
    lead[tid] = leader;
    __syncthreads();

    if (tid == 0) {
        int ng = 0;
        for (int j = 0; j < BB; ++j) {
            if (lead[j]) {
                g_gkey[row * BB + ng] = keys[j];
                g_gcnt[row * BB + ng] = cntb[j];
                ng++;
            }
        }
        g_ng[row] = ng;
    }
}

// =====================================================================
// Layer 0 pooling + GEMM(W0, E=64 -> 4) + relu, writes g_x1.
// Block: 256 threads = 8 warps; warp w handles t = t0+w; lane handles
// e = lane and e = lane+32.
// =====================================================================
__global__ void pool0_kernel(const float* __restrict__ x, const float* __restrict__ W0) {
    const int Brow = blockIdx.x;
    const int t0   = blockIdx.y * 8;
    const int tid  = threadIdx.x;
    const int lane = tid & 31, w = tid >> 5;

    __shared__ float a_s[BB];
    __shared__ unsigned int key_s[BB];
    __shared__ float cnt_s[BB];
    __shared__ float W_s[EE * RR];
    __shared__ int ng_s;

    if (tid < BB) {
        a_s[tid]   = g_adj[Brow * BB + tid];
        key_s[tid] = g_gkey[Brow * BB + tid];
        cnt_s[tid] = g_gcnt[Brow * BB + tid];
    }
    if (tid < EE * RR) W_s[tid] = W0[tid];
    if (tid == 0) ng_s = g_ng[Brow];
    __syncthreads();

    const int t  = t0 + w;
    const int ng = ng_s;
    const int off0 = t * EE + lane;
    const int off1 = off0 + 32;

    float acc0 = 0.f, acc1 = 0.f;
    for (int g = 0; g < ng; ++g) {
        const unsigned int key = key_s[g];
        const float cnt = cnt_s[g];
        const int nm = (key >> 24) & 7;
        unsigned int mm = key;
        float m0 = NEG_INF, m1 = NEG_INF;
        for (int u = 0; u < nm; ++u) {
            const int bp = mm & 63; mm >>= 6;
            const float avv = a_s[bp];
            const float* xp = x + bp * (TT * EE);
            m0 = fmaxf(m0, avv * xp[off0]);
            m1 = fmaxf(m1, avv * xp[off1]);
        }
        if (key >> 28) { m0 = fmaxf(m0, 0.f); m1 = fmaxf(m1, 0.f); }
        acc0 += cnt * m0;
        acc1 += cnt * m1;
    }

    // out[Brow, t, r] = relu(sum_e agg_e * W0[e][r]) via warp butterfly
    float res = 0.f;
#pragma unroll
    for (int rout = 0; rout < RR; ++rout) {
        float p = acc0 * W_s[lane * RR + rout] + acc1 * W_s[(lane + 32) * RR + rout];
        p += __shfl_xor_sync(0xFFFFFFFFu, p, 1);
        p += __shfl_xor_sync(0xFFFFFFFFu, p, 2);
        p += __shfl_xor_sync(0xFFFFFFFFu, p, 4);
        p += __shfl_xor_sync(0xFFFFFFFFu, p, 8);
        p += __shfl_xor_sync(0xFFFFFFFFu, p, 16);
        if (lane == rout) res = p;
    }
    if (lane < RR) g_x1[(Brow * TT + t) * RR + lane] = fmaxf(res, 0.f);
}

// =====================================================================
// Layer 1 pooling + GEMM(W1, 4 -> 4) + relu, reads g_x1 writes g_x2.
// Block: 256 threads = 64 t x 4 r.
// =====================================================================
__global__ void pool1_kernel(const float* __restrict__ W1) {
    const int Brow = blockIdx.x;
    const int t0   = blockIdx.y * 64;
    const int tid  = threadIdx.x;
    const int r    = tid & 3;
    const int tl   = tid >> 2;

    __shared__ float a_s[BB];
    __shared__ unsigned int key_s[BB];
    __shared__ float cnt_s[BB];
    __shared__ float W_s[RR * RR];
    __shared__ int ng_s;

    if (tid < BB) {
        a_s[tid]   = g_adj[Brow * BB + tid];
        key_s[tid] = g_gkey[Brow * BB + tid];
        cnt_s[tid] = g_gcnt[Brow * BB + tid];
    }
    if (tid < RR * RR) W_s[tid] = W1[tid];
    if (tid == 0) ng_s = g_ng[Brow];
    __syncthreads();

    const int t  = t0 + tl;
    const int ng = ng_s;
    const int off = t * RR + r;

    float acc = 0.f;
    for (int g = 0; g < ng; ++g) {
        const unsigned int key = key_s[g];
        const float cnt = cnt_s[g];
        const int nm = (key >> 24) & 7;
        unsigned int mm = key;
        float m = NEG_INF;
        for (int u = 0; u < nm; ++u) {
            const int bp = mm & 63; mm >>= 6;
            m = fmaxf(m, a_s[bp] * g_x1[bp * (TT * RR) + off]);
        }
        if (key >> 28) m = fmaxf(m, 0.f);
        acc += cnt * m;
    }

    // 4->4 matmul across the 4-lane r group
    float res = 0.f;
#pragma unroll
    for (int rout = 0; rout < RR; ++rout) {
        float p = acc * W_s[r * RR + rout];
        p += __shfl_xor_sync(0xFFFFFFFFu, p, 1);
        p += __shfl_xor_sync(0xFFFFFFFFu, p, 2);
        if (r == rout) res = p;
    }
    g_x2[(Brow * TT + t) * RR + r] = fmaxf(res, 0.f);
}

// =====================================================================
// Mean over T, @Wp, softmax. One block per B row.
// =====================================================================
__global__ void final_kernel(const float* __restrict__ Wp, float* __restrict__ outp) {
    const int Brow = blockIdx.x;
    const int tid  = threadIdx.x;   // 256
    const int r    = tid & 3;
    const int tl   = tid >> 2;      // 0..63

    float s = 0.f;
#pragma unroll
    for (int i = 0; i < TT; i += 64) s += g_x2[(Brow * TT + tl + i) * RR + r];

    // reduce over the 8 t's within each warp (r preserved)
    s += __shfl_xor_sync(0xFFFFFFFFu, s, 4);
    s += __shfl_xor_sync(0xFFFFFFFFu, s, 8);
    s += __shfl_xor_sync(0xFFFFFFFFu, s, 16);

    __shared__ float sm[8][4];
    if ((tid & 31) < 4) sm[tid >> 5][r] = s;
    __syncthreads();
    if (tid < 4) {
        float p = 0.f;
        for (int wg = 0; wg < 8; ++wg) p += sm[wg][tid];
        sm[0][tid] = p * (1.0f / (float)TT);
    }
    __syncthreads();
    if (tid == 0) {
        float logit[NSTACK];
        float mx = NEG_INF;
#pragma unroll
        for (int n = 0; n < NSTACK; ++n) {
            float p = 0.f;
#pragma unroll
            for (int rr = 0; rr < RR; ++rr) p += sm[0][rr] * Wp[rr * NSTACK + n];
            logit[n] = p;
            mx = fmaxf(mx, p);
        }
        float se = 0.f;
#pragma unroll
        for (int n = 0; n < NSTACK; ++n) { logit[n] = expf(logit[n] - mx); se += logit[n]; }
        const float inv = 1.0f / se;
#pragma unroll
        for (int n = 0; n < NSTACK; ++n) outp[Brow * NSTACK + n] = logit[n] * inv;
    }
}

// =====================================================================
extern "C" void kernel_launch(void* const* d_in, const int* in_sizes, int n_in,
                              void* d_out, int out_size) {
    const float* x  = (const float*)d_in[0];  // [64,256,64]
    const float* W0 = (const float*)d_in[1];  // [64,4]
    const float* W1 = (const float*)d_in[2];  // [4,4]
    const float* Wp = (const float*)d_in[3];  // [4,8]
    float* out = (float*)d_out;               // [64,8]

    // ---- layer 0 ----
    gram_partial_kernel<TT * EE, false><<<128, 256>>>(x);
    finish_sparsemax_kernel<128><<<BB, BB>>>();
    pool0_kernel<<<dim3(BB, TT / 8), 256>>>(x, W0);

    // ---- layer 1 ----
    gram_partial_kernel<TT * RR, true><<<(TT * RR) / 128, 256>>>(x);
    finish_sparsemax_kernel<(TT * RR) / 128><<<BB, BB>>>();
    pool1_kernel<<<dim3(BB, TT / 64), 256>>>(W1);

    // ---- tail ----
    final_kernel<<<BB, 256>>>(Wp, out);
}